// round 5
// baseline (speedup 1.0000x reference)
#include <cuda_runtime.h>
#include <cstdint>

// Problem dims
#define Bq   8
#define Nq   8192
#define Sq   2048
#define D1q  128
#define D2q  256
#define KIN  384          // D1 + D2
#define C1   256          // layer-1 out channels
#define C2   128          // layer-2 out channels
#define MROWS (Bq * Nq)   // 65536

// ---------------------------------------------------------------------------
// Scratch (device globals — no allocation allowed)
// ---------------------------------------------------------------------------
__device__ float g_x  [(size_t)MROWS * KIN];   // concat(f1, interp)  [M, 384]
__device__ float g_y1 [(size_t)MROWS * C1];    // linear1 out         [M, 256]
__device__ float g_y2 [(size_t)MROWS * C2];    // linear2 out         [M, 128]
__device__ float g_f2t[(size_t)Bq * Sq * D2q]; // points2 transposed  [B, S, 256]
__device__ int   g_idx[(size_t)Bq * Nq * 3];
__device__ float g_wts[(size_t)Bq * Nq * 3];
__device__ float g_part[128 * 2 * C1];         // per-block partial sums (max C1)
__device__ float g_scale1[C1], g_shift1[C1];
__device__ float g_scale2[C2], g_shift2[C2];

// ---------------------------------------------------------------------------
// Transpose points2 [B, D2, S] -> g_f2t [B, S, D2]
// ---------------------------------------------------------------------------
__global__ void transpose_p2_kernel(const float* __restrict__ p2) {
    __shared__ float tile[32][33];
    int b  = blockIdx.z;
    int s0 = blockIdx.x * 32, d0 = blockIdx.y * 32;
    int tx = threadIdx.x, ty = threadIdx.y;          // 32 x 8
    const float* src = p2 + (size_t)b * D2q * Sq;
    #pragma unroll
    for (int i = ty; i < 32; i += 8)
        tile[i][tx] = src[(size_t)(d0 + i) * Sq + s0 + tx];
    __syncthreads();
    float* dst = g_f2t + (size_t)b * Sq * D2q;
    #pragma unroll
    for (int i = ty; i < 32; i += 8)
        dst[(size_t)(s0 + i) * D2q + d0 + tx] = tile[tx][i];
}

// ---------------------------------------------------------------------------
// Transpose points1 [B, D1, N] into g_x columns [0, 128)
// ---------------------------------------------------------------------------
__global__ void transpose_p1_kernel(const float* __restrict__ p1) {
    __shared__ float tile[32][33];
    int b  = blockIdx.z;
    int n0 = blockIdx.x * 32, d0 = blockIdx.y * 32;
    int tx = threadIdx.x, ty = threadIdx.y;          // 32 x 8
    const float* src = p1 + (size_t)b * D1q * Nq;
    #pragma unroll
    for (int i = ty; i < 32; i += 8)
        tile[i][tx] = src[(size_t)(d0 + i) * Nq + n0 + tx];
    __syncthreads();
    #pragma unroll
    for (int i = ty; i < 32; i += 8)
        g_x[((size_t)b * Nq + n0 + i) * KIN + d0 + tx] = tile[tx][i];
}

// ---------------------------------------------------------------------------
// 3-NN + weights. One thread per query point; xyz2(+|p2|^2) staged in SMEM.
// Distance uses the same |p1|^2 + |p2|^2 - 2*dot expansion as the reference.
// ---------------------------------------------------------------------------
__global__ void knn_kernel(const float* __restrict__ xyz1,
                           const float* __restrict__ xyz2) {
    __shared__ float sx[Sq], sy[Sq], sz[Sq], sn[Sq];
    int b = blockIdx.y;
    const float* x2 = xyz2 + (size_t)b * 3 * Sq;
    for (int s = threadIdx.x; s < Sq; s += blockDim.x) {
        float xx = x2[s], yy = x2[Sq + s], zz = x2[2 * Sq + s];
        sx[s] = xx; sy[s] = yy; sz[s] = zz;
        sn[s] = fmaf(xx, xx, fmaf(yy, yy, zz * zz));
    }
    __syncthreads();

    int n = blockIdx.x * blockDim.x + threadIdx.x;
    const float* x1 = xyz1 + (size_t)b * 3 * Nq;
    float px = x1[n], py = x1[Nq + n], pz = x1[2 * Nq + n];
    float n1 = fmaf(px, px, fmaf(py, py, pz * pz));

    float d0 = 3.4e38f, d1 = 3.4e38f, d2 = 3.4e38f;
    int   i0 = 0, i1 = 0, i2 = 0;
    #pragma unroll 4
    for (int s = 0; s < Sq; s++) {
        float dot = fmaf(px, sx[s], fmaf(py, sy[s], pz * sz[s]));
        float d   = fmaf(-2.0f, dot, n1 + sn[s]);
        if (d < d2) {
            if (d < d1) {
                d2 = d1; i2 = i1;
                if (d < d0) { d1 = d0; i1 = i0; d0 = d; i0 = s; }
                else        { d1 = d;  i1 = s; }
            } else { d2 = d; i2 = s; }
        }
    }
    d0 = fmaxf(d0, 1e-10f); d1 = fmaxf(d1, 1e-10f); d2 = fmaxf(d2, 1e-10f);
    float w0 = 1.0f / d0, w1 = 1.0f / d1, w2 = 1.0f / d2;
    float inv = 1.0f / (w0 + w1 + w2);
    size_t base = ((size_t)b * Nq + n) * 3;
    g_idx[base] = i0; g_idx[base + 1] = i1; g_idx[base + 2] = i2;
    g_wts[base] = w0 * inv; g_wts[base + 1] = w1 * inv; g_wts[base + 2] = w2 * inv;
}

// ---------------------------------------------------------------------------
// Interpolate: g_x[:, 128:384] = sum_j w_j * f2t[idx_j].  One block per point.
// ---------------------------------------------------------------------------
__global__ void interp_kernel() {
    int b = blockIdx.y;
    int n = blockIdx.x;
    int d = threadIdx.x;                              // 256 threads = D2
    size_t qb = (size_t)b * Nq + n;
    const int*   ip = g_idx + qb * 3;
    const float* wp = g_wts + qb * 3;
    const float* f  = g_f2t + (size_t)b * Sq * D2q;
    float acc = wp[0] * f[(size_t)ip[0] * D2q + d];
    acc = fmaf(wp[1], f[(size_t)ip[1] * D2q + d], acc);
    acc = fmaf(wp[2], f[(size_t)ip[2] * D2q + d], acc);
    g_x[qb * KIN + D1q + d] = acc;
}

// ---------------------------------------------------------------------------
// SGEMM 1: y1[M,256] = x[M,384] @ w1^T + b1
// 128x128x16 block tile, 8x8 per thread, 256 threads.
// ---------------------------------------------------------------------------
__global__ __launch_bounds__(256) void gemm1_kernel(const float* __restrict__ W,
                                                    const float* __restrict__ bias) {
    __shared__ float As[16][128];
    __shared__ float Bs[16][128];
    int tid  = threadIdx.x;
    int row0 = blockIdx.y * 128;
    int col0 = blockIdx.x * 128;
    int tx = tid & 15, ty = tid >> 4;
    float acc[8][8] = {};
    const float* Ag = g_x + (size_t)row0 * KIN;
    const float* Wg = W   + (size_t)col0 * KIN;

    for (int k0 = 0; k0 < KIN; k0 += 16) {
        #pragma unroll
        for (int i = 0; i < 2; i++) {
            int slot = tid + i * 256;
            int r = slot >> 2, kk = (slot & 3) << 2;
            float4 v = *(const float4*)(Ag + (size_t)r * KIN + k0 + kk);
            As[kk][r] = v.x; As[kk + 1][r] = v.y; As[kk + 2][r] = v.z; As[kk + 3][r] = v.w;
            float4 u = *(const float4*)(Wg + (size_t)r * KIN + k0 + kk);
            Bs[kk][r] = u.x; Bs[kk + 1][r] = u.y; Bs[kk + 2][r] = u.z; Bs[kk + 3][r] = u.w;
        }
        __syncthreads();
        #pragma unroll
        for (int k = 0; k < 16; k++) {
            float a[8], bb[8];
            #pragma unroll
            for (int i = 0; i < 8; i++) a[i]  = As[k][ty * 8 + i];
            #pragma unroll
            for (int j = 0; j < 8; j++) bb[j] = Bs[k][tx * 8 + j];
            #pragma unroll
            for (int i = 0; i < 8; i++)
                #pragma unroll
                for (int j = 0; j < 8; j++)
                    acc[i][j] = fmaf(a[i], bb[j], acc[i][j]);
        }
        __syncthreads();
    }
    float bcol[8];
    #pragma unroll
    for (int j = 0; j < 8; j++) bcol[j] = bias[col0 + tx * 8 + j];
    #pragma unroll
    for (int i = 0; i < 8; i++) {
        float* cp = g_y1 + (size_t)(row0 + ty * 8 + i) * C1 + col0 + tx * 8;
        float4 v0 = {acc[i][0] + bcol[0], acc[i][1] + bcol[1],
                     acc[i][2] + bcol[2], acc[i][3] + bcol[3]};
        float4 v1 = {acc[i][4] + bcol[4], acc[i][5] + bcol[5],
                     acc[i][6] + bcol[6], acc[i][7] + bcol[7]};
        *(float4*)cp = v0; *(float4*)(cp + 4) = v1;
    }
}

// ---------------------------------------------------------------------------
// BN stats, two deterministic stages. layer 0 -> y1/C1, layer 1 -> y2/C2.
// ---------------------------------------------------------------------------
__global__ void stats_stage1_kernel(int layer) {
    int C = layer ? C2 : C1;
    const float* Y = layer ? g_y2 : g_y1;
    int ch = threadIdx.x;
    size_t r0 = (size_t)blockIdx.x * 512;
    float s = 0.0f, sq = 0.0f;
    for (int r = 0; r < 512; r++) {
        float v = Y[(r0 + r) * C + ch];
        s += v;
        sq = fmaf(v, v, sq);
    }
    g_part[blockIdx.x * 2 * C + ch]     = s;
    g_part[blockIdx.x * 2 * C + C + ch] = sq;
}

__global__ void stats_stage2_kernel(int layer, const float* __restrict__ g,
                                    const float* __restrict__ be) {
    int C  = layer ? C2 : C1;
    int ch = threadIdx.x;
    float s = 0.0f, sq = 0.0f;
    for (int bk = 0; bk < 128; bk++) {
        s  += g_part[bk * 2 * C + ch];
        sq += g_part[bk * 2 * C + C + ch];
    }
    const float invM = 1.0f / (float)MROWS;
    float mean = s * invM;
    float var  = fmaf(sq, invM, -mean * mean);
    float scv  = g[ch] * rsqrtf(var + 1e-5f);
    float shv  = fmaf(-mean, scv, be[ch]);
    if (layer) { g_scale2[ch] = scv; g_shift2[ch] = shv; }
    else       { g_scale1[ch] = scv; g_shift1[ch] = shv; }
}

// ---------------------------------------------------------------------------
// SGEMM 2: y2[M,128] = relu(bn(y1))[M,256] @ w2^T + b2
// BN+ReLU fused into the A-tile load.
// ---------------------------------------------------------------------------
__global__ __launch_bounds__(256) void gemm2_kernel(const float* __restrict__ W,
                                                    const float* __restrict__ bias) {
    __shared__ float As[16][128];
    __shared__ float Bs[16][128];
    __shared__ float sc[C1], sh[C1];
    int tid  = threadIdx.x;
    sc[tid] = g_scale1[tid];
    sh[tid] = g_shift1[tid];
    __syncthreads();

    int row0 = blockIdx.y * 128;
    int col0 = blockIdx.x * 128;
    int tx = tid & 15, ty = tid >> 4;
    float acc[8][8] = {};
    const float* Ag = g_y1 + (size_t)row0 * C1;
    const float* Wg = W    + (size_t)col0 * C1;

    for (int k0 = 0; k0 < C1; k0 += 16) {
        #pragma unroll
        for (int i = 0; i < 2; i++) {
            int slot = tid + i * 256;
            int r = slot >> 2, kk = (slot & 3) << 2;
            float4 v = *(const float4*)(Ag + (size_t)r * C1 + k0 + kk);
            As[kk][r]     = fmaxf(fmaf(v.x, sc[k0 + kk],     sh[k0 + kk]),     0.0f);
            As[kk + 1][r] = fmaxf(fmaf(v.y, sc[k0 + kk + 1], sh[k0 + kk + 1]), 0.0f);
            As[kk + 2][r] = fmaxf(fmaf(v.z, sc[k0 + kk + 2], sh[k0 + kk + 2]), 0.0f);
            As[kk + 3][r] = fmaxf(fmaf(v.w, sc[k0 + kk + 3], sh[k0 + kk + 3]), 0.0f);
            float4 u = *(const float4*)(Wg + (size_t)r * C1 + k0 + kk);
            Bs[kk][r] = u.x; Bs[kk + 1][r] = u.y; Bs[kk + 2][r] = u.z; Bs[kk + 3][r] = u.w;
        }
        __syncthreads();
        #pragma unroll
        for (int k = 0; k < 16; k++) {
            float a[8], bb[8];
            #pragma unroll
            for (int i = 0; i < 8; i++) a[i]  = As[k][ty * 8 + i];
            #pragma unroll
            for (int j = 0; j < 8; j++) bb[j] = Bs[k][tx * 8 + j];
            #pragma unroll
            for (int i = 0; i < 8; i++)
                #pragma unroll
                for (int j = 0; j < 8; j++)
                    acc[i][j] = fmaf(a[i], bb[j], acc[i][j]);
        }
        __syncthreads();
    }
    float bcol[8];
    #pragma unroll
    for (int j = 0; j < 8; j++) bcol[j] = bias[col0 + tx * 8 + j];
    #pragma unroll
    for (int i = 0; i < 8; i++) {
        float* cp = g_y2 + (size_t)(row0 + ty * 8 + i) * C2 + col0 + tx * 8;
        float4 v0 = {acc[i][0] + bcol[0], acc[i][1] + bcol[1],
                     acc[i][2] + bcol[2], acc[i][3] + bcol[3]};
        float4 v1 = {acc[i][4] + bcol[4], acc[i][5] + bcol[5],
                     acc[i][6] + bcol[6], acc[i][7] + bcol[7]};
        *(float4*)cp = v0; *(float4*)(cp + 4) = v1;
    }
}

// ---------------------------------------------------------------------------
// Epilogue: out[b, c, n] = relu(bn2(y2[b*N+n, c])), transposed write
// ---------------------------------------------------------------------------
__global__ void epilogue_kernel(float* __restrict__ out) {
    __shared__ float tile[32][33];
    int b  = blockIdx.z;
    int n0 = blockIdx.x * 32, c0 = blockIdx.y * 32;
    int tx = threadIdx.x, ty = threadIdx.y;           // 32 x 8
    #pragma unroll
    for (int i = ty; i < 32; i += 8) {
        float v = g_y2[((size_t)b * Nq + n0 + i) * C2 + c0 + tx];
        tile[i][tx] = fmaxf(fmaf(v, g_scale2[c0 + tx], g_shift2[c0 + tx]), 0.0f);
    }
    __syncthreads();
    #pragma unroll
    for (int i = ty; i < 32; i += 8)
        out[(size_t)b * C2 * Nq + (size_t)(c0 + i) * Nq + n0 + tx] = tile[tx][i];
}

// ---------------------------------------------------------------------------
// Launch
// ---------------------------------------------------------------------------
extern "C" void kernel_launch(void* const* d_in, const int* in_sizes, int n_in,
                              void* d_out, int out_size) {
    const float* xyz1    = (const float*)d_in[0];
    const float* xyz2    = (const float*)d_in[1];
    const float* points1 = (const float*)d_in[2];
    const float* points2 = (const float*)d_in[3];
    const float* w1      = (const float*)d_in[4];
    const float* b1      = (const float*)d_in[5];
    const float* g1      = (const float*)d_in[6];
    const float* be1     = (const float*)d_in[7];
    const float* w2      = (const float*)d_in[8];
    const float* b2      = (const float*)d_in[9];
    const float* g2      = (const float*)d_in[10];
    const float* be2     = (const float*)d_in[11];
    float* out = (float*)d_out;

    dim3 tb(32, 8);
    transpose_p2_kernel<<<dim3(Sq / 32, D2q / 32, Bq), tb>>>(points2);
    transpose_p1_kernel<<<dim3(Nq / 32, D1q / 32, Bq), tb>>>(points1);
    knn_kernel<<<dim3(Nq / 128, Bq), 128>>>(xyz1, xyz2);
    interp_kernel<<<dim3(Nq, Bq), D2q>>>();
    gemm1_kernel<<<dim3(C1 / 128, MROWS / 128), 256>>>(w1, b1);
    stats_stage1_kernel<<<128, C1>>>(0);
    stats_stage2_kernel<<<1, C1>>>(0, g1, be1);
    gemm2_kernel<<<dim3(C2 / 128, MROWS / 128), 256>>>(w2, b2);
    stats_stage1_kernel<<<128, C2>>>(1);
    stats_stage2_kernel<<<1, C2>>>(1, g2, be2);
    epilogue_kernel<<<dim3(Nq / 32, C2 / 32, Bq), tb>>>(out);
}

// round 8
// speedup vs baseline: 1.5528x; 1.5528x over previous
#include <cuda_runtime.h>
#include <cuda_bf16.h>
#include <cstdint>

// Problem dims
#define Bq   8
#define Nq   8192
#define Sq   2048
#define D1q  128
#define D2q  256
#define KIN  384          // D1 + D2
#define C1   256          // layer-1 out channels
#define C2   128          // layer-2 out channels
#define MROWS (Bq * Nq)   // 65536

// ---------------------------------------------------------------------------
// Scratch (device globals — no allocation allowed)
// ---------------------------------------------------------------------------
__device__ __align__(16) __nv_bfloat16 g_xh[(size_t)MROWS * KIN];  // bf16 hi (reused [M][256] for GEMM2 A)
__device__ __align__(16) __nv_bfloat16 g_xl[(size_t)MROWS * KIN];  // bf16 lo
__device__ __align__(16) float g_y1 [(size_t)MROWS * C1];          // linear1 out fp32
__device__ __align__(16) float g_y2 [(size_t)MROWS * C2];          // linear2 out fp32
__device__ __align__(16) float g_f2t[(size_t)Bq * Sq * D2q];       // points2 transposed
__device__ int   g_idx[(size_t)Bq * Nq * 3];
__device__ float g_wts[(size_t)Bq * Nq * 3];
__device__ float g_part[128 * 2 * C1];
__device__ float g_scale1[C1], g_shift1[C1];
__device__ float g_scale2[C2], g_shift2[C2];
__device__ __align__(16) __nv_bfloat16 g_w1h[C1 * KIN], g_w1l[C1 * KIN];
__device__ __align__(16) __nv_bfloat16 g_w2h[C2 * C1],  g_w2l[C2 * C1];

// ---------------------------------------------------------------------------
// PTX helpers — ONLY family-portable instructions (sm_80+): cp.async,
// ldmatrix, mma.sync. No tcgen05 anywhere (ptxas here targets plain sm_103).
// ---------------------------------------------------------------------------
__device__ __forceinline__ uint32_t smem_u32(const void* p) {
    uint32_t a;
    asm("{ .reg .u64 t; cvta.to.shared.u64 t, %1; cvt.u32.u64 %0, t; }"
        : "=r"(a) : "l"(p));
    return a;
}
__device__ __forceinline__ void cp16(uint32_t s, const void* g) {
    asm volatile("cp.async.cg.shared.global [%0], [%1], 16;" :: "r"(s), "l"(g) : "memory");
}
__device__ __forceinline__ void cp_commit() {
    asm volatile("cp.async.commit_group;" ::: "memory");
}
template <int N> __device__ __forceinline__ void cp_wait() {
    asm volatile("cp.async.wait_group %0;" :: "n"(N) : "memory");
}
#define LDMX4(r, addr) \
    asm volatile("ldmatrix.sync.aligned.m8n8.x4.shared.b16 {%0,%1,%2,%3}, [%4];" \
        : "=r"((r)[0]), "=r"((r)[1]), "=r"((r)[2]), "=r"((r)[3]) : "r"(addr))

__device__ __forceinline__ void mma16816(float* d, const uint32_t* a,
                                         uint32_t b0, uint32_t b1) {
    asm volatile(
        "mma.sync.aligned.m16n8k16.row.col.f32.bf16.bf16.f32 "
        "{%0,%1,%2,%3}, {%4,%5,%6,%7}, {%8,%9}, {%0,%1,%2,%3};"
        : "+f"(d[0]), "+f"(d[1]), "+f"(d[2]), "+f"(d[3])
        : "r"(a[0]), "r"(a[1]), "r"(a[2]), "r"(a[3]), "r"(b0), "r"(b1));
}

__device__ __forceinline__ void bf16_split(float v, __nv_bfloat16& h, __nv_bfloat16& l) {
    h = __float2bfloat16(v);
    l = __float2bfloat16(v - __bfloat162float(h));
}

// ---------------------------------------------------------------------------
// Weight pre-split: fp32 -> bf16 hi/lo
// ---------------------------------------------------------------------------
__global__ void conv_w_kernel(const float* __restrict__ w1, const float* __restrict__ w2) {
    int i = blockIdx.x * 256 + threadIdx.x;
    if (i < C1 * KIN) {
        __nv_bfloat16 h, l; bf16_split(w1[i], h, l);
        g_w1h[i] = h; g_w1l[i] = l;
    }
    if (i < C2 * C1) {
        __nv_bfloat16 h, l; bf16_split(w2[i], h, l);
        g_w2h[i] = h; g_w2l[i] = l;
    }
}

// ---------------------------------------------------------------------------
// Transpose points2 [B, D2, S] -> g_f2t [B, S, D2]
// ---------------------------------------------------------------------------
__global__ void transpose_p2_kernel(const float* __restrict__ p2) {
    __shared__ float tile[32][33];
    int b  = blockIdx.z;
    int s0 = blockIdx.x * 32, d0 = blockIdx.y * 32;
    int tx = threadIdx.x, ty = threadIdx.y;
    const float* src = p2 + (size_t)b * D2q * Sq;
    #pragma unroll
    for (int i = ty; i < 32; i += 8)
        tile[i][tx] = src[(size_t)(d0 + i) * Sq + s0 + tx];
    __syncthreads();
    float* dst = g_f2t + (size_t)b * Sq * D2q;
    #pragma unroll
    for (int i = ty; i < 32; i += 8)
        dst[(size_t)(s0 + i) * D2q + d0 + tx] = tile[tx][i];
}

// ---------------------------------------------------------------------------
// Transpose points1 [B, D1, N] -> g_xh/g_xl columns [0, 128)
// ---------------------------------------------------------------------------
__global__ void transpose_p1_kernel(const float* __restrict__ p1) {
    __shared__ float tile[32][33];
    int b  = blockIdx.z;
    int n0 = blockIdx.x * 32, d0 = blockIdx.y * 32;
    int tx = threadIdx.x, ty = threadIdx.y;
    const float* src = p1 + (size_t)b * D1q * Nq;
    #pragma unroll
    for (int i = ty; i < 32; i += 8)
        tile[i][tx] = src[(size_t)(d0 + i) * Nq + n0 + tx];
    __syncthreads();
    #pragma unroll
    for (int i = ty; i < 32; i += 8) {
        float v = tile[tx][i];
        __nv_bfloat16 h, l; bf16_split(v, h, l);
        size_t o = ((size_t)b * Nq + n0 + i) * KIN + d0 + tx;
        g_xh[o] = h; g_xl[o] = l;
    }
}

// ---------------------------------------------------------------------------
// 3-NN + weights
// ---------------------------------------------------------------------------
__global__ void knn_kernel(const float* __restrict__ xyz1,
                           const float* __restrict__ xyz2) {
    __shared__ float sx[Sq], sy[Sq], sz[Sq], sn[Sq];
    int b = blockIdx.y;
    const float* x2 = xyz2 + (size_t)b * 3 * Sq;
    for (int s = threadIdx.x; s < Sq; s += blockDim.x) {
        float xx = x2[s], yy = x2[Sq + s], zz = x2[2 * Sq + s];
        sx[s] = xx; sy[s] = yy; sz[s] = zz;
        sn[s] = fmaf(xx, xx, fmaf(yy, yy, zz * zz));
    }
    __syncthreads();

    int n = blockIdx.x * blockDim.x + threadIdx.x;
    const float* x1 = xyz1 + (size_t)b * 3 * Nq;
    float px = x1[n], py = x1[Nq + n], pz = x1[2 * Nq + n];
    float n1 = fmaf(px, px, fmaf(py, py, pz * pz));

    float d0 = 3.4e38f, d1 = 3.4e38f, d2 = 3.4e38f;
    int   i0 = 0, i1 = 0, i2 = 0;
    #pragma unroll 4
    for (int s = 0; s < Sq; s++) {
        float dot = fmaf(px, sx[s], fmaf(py, sy[s], pz * sz[s]));
        float d   = fmaf(-2.0f, dot, n1 + sn[s]);
        if (d < d2) {
            if (d < d1) {
                d2 = d1; i2 = i1;
                if (d < d0) { d1 = d0; i1 = i0; d0 = d; i0 = s; }
                else        { d1 = d;  i1 = s; }
            } else { d2 = d; i2 = s; }
        }
    }
    d0 = fmaxf(d0, 1e-10f); d1 = fmaxf(d1, 1e-10f); d2 = fmaxf(d2, 1e-10f);
    float w0 = 1.0f / d0, w1 = 1.0f / d1, w2 = 1.0f / d2;
    float inv = 1.0f / (w0 + w1 + w2);
    size_t base = ((size_t)b * Nq + n) * 3;
    g_idx[base] = i0; g_idx[base + 1] = i1; g_idx[base + 2] = i2;
    g_wts[base] = w0 * inv; g_wts[base + 1] = w1 * inv; g_wts[base + 2] = w2 * inv;
}

// ---------------------------------------------------------------------------
// Interpolate -> g_xh/g_xl columns [128, 384). 64 threads per point, float4.
// ---------------------------------------------------------------------------
__global__ void interp_kernel() {
    int b  = blockIdx.y;
    int pt = blockIdx.x * 4 + (threadIdx.x >> 6);
    int t  = threadIdx.x & 63;
    size_t qb = (size_t)b * Nq + pt;
    const int*   ip = g_idx + qb * 3;
    const float* wp = g_wts + qb * 3;
    const float* f  = g_f2t + (size_t)b * Sq * D2q;
    int d = t * 4;
    float4 f0 = *(const float4*)(f + (size_t)ip[0] * D2q + d);
    float4 f1 = *(const float4*)(f + (size_t)ip[1] * D2q + d);
    float4 f2 = *(const float4*)(f + (size_t)ip[2] * D2q + d);
    float w0 = wp[0], w1 = wp[1], w2 = wp[2];
    float a0 = fmaf(w2, f2.x, fmaf(w1, f1.x, w0 * f0.x));
    float a1 = fmaf(w2, f2.y, fmaf(w1, f1.y, w0 * f0.y));
    float a2 = fmaf(w2, f2.z, fmaf(w1, f1.z, w0 * f0.z));
    float a3 = fmaf(w2, f2.w, fmaf(w1, f1.w, w0 * f0.w));
    __nv_bfloat16 h0, l0, h1, l1, h2, l2, h3, l3;
    bf16_split(a0, h0, l0); bf16_split(a1, h1, l1);
    bf16_split(a2, h2, l2); bf16_split(a3, h3, l3);
    uint32_t ph0 = ((uint32_t)__bfloat16_as_ushort(h1) << 16) | __bfloat16_as_ushort(h0);
    uint32_t ph1 = ((uint32_t)__bfloat16_as_ushort(h3) << 16) | __bfloat16_as_ushort(h2);
    uint32_t pl0 = ((uint32_t)__bfloat16_as_ushort(l1) << 16) | __bfloat16_as_ushort(l0);
    uint32_t pl1 = ((uint32_t)__bfloat16_as_ushort(l3) << 16) | __bfloat16_as_ushort(l2);
    uint2 vh = {ph0, ph1}, vl = {pl0, pl1};
    size_t o = qb * KIN + D1q + d;
    *(uint2*)(g_xh + o) = vh;
    *(uint2*)(g_xl + o) = vl;
}

// ---------------------------------------------------------------------------
// HMMA GEMM (mma.sync m16n8k16 bf16 -> f32), 3-pass hi/lo split.
// Block 128x128, 8 warps (4 M x 2 N), warp tile 32x64, K-chunk 32,
// cp.async double buffer, 80B-padded SMEM rows (conflict-free ldmatrix).
// WHICH=1: y1[M,256] = x[M,384] @ w1^T     (A=g_xh/g_xl LDA=384)
// WHICH=2: y2[M,128] = a2[M,256] @ w2^T    (A=reused g_xh/g_xl LDA=256)
// ---------------------------------------------------------------------------
template <int WHICH>
__global__ __launch_bounds__(256) void gemm_hmma() {
    constexpr int LDA = (WHICH == 1) ? KIN : C1;
    constexpr int LDB = (WHICH == 1) ? KIN : C1;
    constexpr int KD  = (WHICH == 1) ? KIN : C1;
    constexpr int LDC = (WHICH == 1) ? C1  : C2;
    constexpr int KC  = KD / 32;
    constexpr int NITER = 3 * KC;

    const __nv_bfloat16* Ah = g_xh;
    const __nv_bfloat16* Al = g_xl;
    const __nv_bfloat16* Bh = (WHICH == 1) ? g_w1h : g_w2h;
    const __nv_bfloat16* Bl = (WHICH == 1) ? g_w1l : g_w2l;
    float* Cout = (WHICH == 1) ? g_y1 : g_y2;

    __shared__ __align__(16) char smA[2][128 * 80];
    __shared__ __align__(16) char smB[2][128 * 80];

    const int tid = threadIdx.x, lane = tid & 31, wid = tid >> 5;
    const int warp_m = wid & 3, warp_n = wid >> 2;
    const size_t row0 = (size_t)blockIdx.y * 128;
    const int col0 = blockIdx.x * 128;

    const uint32_t sAu[2] = { smem_u32(smA[0]), smem_u32(smA[1]) };
    const uint32_t sBu[2] = { smem_u32(smB[0]), smem_u32(smB[1]) };

    // ldmatrix per-lane base offsets (bytes)
    const uint32_t a_off = (uint32_t)((warp_m * 32 + ((lane >> 3) & 1) * 8 + (lane & 7)) * 80
                                      + (lane >> 4) * 16);
    const uint32_t b_off = (uint32_t)((warp_n * 64 + (lane >> 4) * 8 + (lane & 7)) * 80
                                      + ((lane >> 3) & 1) * 16);

    float acc[2][8][4] = {};

    auto issue = [&](int it, int buf) {
        const int p  = it / KC;
        const int k0 = (it - p * KC) * 32;
        const char* As = (const char*)((p == 1) ? Al : Ah);
        const char* Bs = (const char*)((p == 2) ? Bl : Bh);
        #pragma unroll
        for (int i = 0; i < 2; i++) {
            int c = tid + i * 256;
            int r = c >> 2, cc = c & 3;
            cp16(sAu[buf] + r * 80 + cc * 16,
                 As + ((row0 + r) * LDA + k0) * 2 + cc * 16);
            cp16(sBu[buf] + r * 80 + cc * 16,
                 Bs + ((size_t)(col0 + r) * LDB + k0) * 2 + cc * 16);
        }
        cp_commit();
    };

    issue(0, 0);
    for (int it = 0; it < NITER; it++) {
        const int buf = it & 1;
        if (it + 1 < NITER) { issue(it + 1, buf ^ 1); cp_wait<1>(); }
        else                { cp_wait<0>(); }
        __syncthreads();

        #pragma unroll
        for (int ks = 0; ks < 2; ks++) {
            uint32_t af[2][4];
            LDMX4(af[0], sAu[buf] + a_off + ks * 32);
            LDMX4(af[1], sAu[buf] + a_off + 16 * 80 + ks * 32);
            uint32_t bfr[4][4];
            #pragma unroll
            for (int jp = 0; jp < 4; jp++)
                LDMX4(bfr[jp], sBu[buf] + b_off + jp * 16 * 80 + ks * 32);
            #pragma unroll
            for (int mt = 0; mt < 2; mt++)
                #pragma unroll
                for (int j = 0; j < 8; j++)
                    mma16816(acc[mt][j], af[mt],
                             bfr[j >> 1][(j & 1) * 2], bfr[j >> 1][(j & 1) * 2 + 1]);
        }
        __syncthreads();
    }

    // Store: c0,c1 -> (row, col..col+1); c2,c3 -> (row+8, ...)
    #pragma unroll
    for (int mt = 0; mt < 2; mt++) {
        #pragma unroll
        for (int j = 0; j < 8; j++) {
            size_t row = row0 + warp_m * 32 + mt * 16 + (lane >> 2);
            int    col = col0 + warp_n * 64 + j * 8 + 2 * (lane & 3);
            float* p0 = Cout + row * LDC + col;
            float2 v0 = { acc[mt][j][0], acc[mt][j][1] };
            float2 v1 = { acc[mt][j][2], acc[mt][j][3] };
            *(float2*)p0 = v0;
            *(float2*)(p0 + 8 * LDC) = v1;
        }
    }
}

// ---------------------------------------------------------------------------
// BN stats (two deterministic stages)
// ---------------------------------------------------------------------------
__global__ void stats_stage1_kernel(int layer) {
    int C = layer ? C2 : C1;
    const float* Y = layer ? g_y2 : g_y1;
    int ch = threadIdx.x;
    size_t r0 = (size_t)blockIdx.x * 512;
    float s = 0.0f, sq = 0.0f;
    for (int r = 0; r < 512; r++) {
        float v = Y[(r0 + r) * C + ch];
        s += v;
        sq = fmaf(v, v, sq);
    }
    g_part[blockIdx.x * 2 * C + ch]     = s;
    g_part[blockIdx.x * 2 * C + C + ch] = sq;
}

__global__ void stats_stage2_kernel(int layer, const float* __restrict__ g,
                                    const float* __restrict__ be) {
    int C  = layer ? C2 : C1;
    int ch = threadIdx.x;
    float s = 0.0f, sq = 0.0f;
    for (int bk = 0; bk < 128; bk++) {
        s  += g_part[bk * 2 * C + ch];
        sq += g_part[bk * 2 * C + C + ch];
    }
    const float invM = 1.0f / (float)MROWS;
    float mean = s * invM;
    float var  = fmaf(sq, invM, -mean * mean);
    float scv  = g[ch] * rsqrtf(var + 1e-5f);
    float shv  = fmaf(-mean, scv, be[ch]);
    if (layer) { g_scale2[ch] = scv; g_shift2[ch] = shv; }
    else       { g_scale1[ch] = scv; g_shift1[ch] = shv; }
}

// ---------------------------------------------------------------------------
// BN+ReLU+bf16-split of y1 -> g_xh/g_xl reused as [M][256] (GEMM2 A operand)
// ---------------------------------------------------------------------------
__global__ void bnrelu_split_kernel() {
    size_t i = ((size_t)blockIdx.x * 256 + threadIdx.x) * 4;  // over MROWS*C1
    float4 v = *(const float4*)(g_y1 + i);
    int ch = (int)(i & (C1 - 1));
    float a0 = fmaxf(fmaf(v.x, g_scale1[ch],     g_shift1[ch]),     0.0f);
    float a1 = fmaxf(fmaf(v.y, g_scale1[ch + 1], g_shift1[ch + 1]), 0.0f);
    float a2 = fmaxf(fmaf(v.z, g_scale1[ch + 2], g_shift1[ch + 2]), 0.0f);
    float a3 = fmaxf(fmaf(v.w, g_scale1[ch + 3], g_shift1[ch + 3]), 0.0f);
    __nv_bfloat16 h0, l0, h1, l1, h2, l2, h3, l3;
    bf16_split(a0, h0, l0); bf16_split(a1, h1, l1);
    bf16_split(a2, h2, l2); bf16_split(a3, h3, l3);
    uint32_t ph0 = ((uint32_t)__bfloat16_as_ushort(h1) << 16) | __bfloat16_as_ushort(h0);
    uint32_t ph1 = ((uint32_t)__bfloat16_as_ushort(h3) << 16) | __bfloat16_as_ushort(h2);
    uint32_t pl0 = ((uint32_t)__bfloat16_as_ushort(l1) << 16) | __bfloat16_as_ushort(l0);
    uint32_t pl1 = ((uint32_t)__bfloat16_as_ushort(l3) << 16) | __bfloat16_as_ushort(l2);
    uint2 vh = {ph0, ph1}, vl = {pl0, pl1};
    *(uint2*)(g_xh + i) = vh;
    *(uint2*)(g_xl + i) = vl;
}

// ---------------------------------------------------------------------------
// Final epilogue: out[b, c, n] = relu(bn2(y2)), transposed write
// ---------------------------------------------------------------------------
__global__ void epilogue_kernel(float* __restrict__ out) {
    __shared__ float tile[32][33];
    int b  = blockIdx.z;
    int n0 = blockIdx.x * 32, c0 = blockIdx.y * 32;
    int tx = threadIdx.x, ty = threadIdx.y;
    #pragma unroll
    for (int i = ty; i < 32; i += 8) {
        float v = g_y2[((size_t)b * Nq + n0 + i) * C2 + c0 + tx];
        tile[i][tx] = fmaxf(fmaf(v, g_scale2[c0 + tx], g_shift2[c0 + tx]), 0.0f);
    }
    __syncthreads();
    #pragma unroll
    for (int i = ty; i < 32; i += 8)
        out[(size_t)b * C2 * Nq + (size_t)(c0 + i) * Nq + n0 + tx] = tile[tx][i];
}

// ---------------------------------------------------------------------------
// Launch
// ---------------------------------------------------------------------------
extern "C" void kernel_launch(void* const* d_in, const int* in_sizes, int n_in,
                              void* d_out, int out_size) {
    const float* xyz1    = (const float*)d_in[0];
    const float* xyz2    = (const float*)d_in[1];
    const float* points1 = (const float*)d_in[2];
    const float* points2 = (const float*)d_in[3];
    const float* w1      = (const float*)d_in[4];
    const float* g1      = (const float*)d_in[6];
    const float* be1     = (const float*)d_in[7];
    const float* w2      = (const float*)d_in[8];
    const float* g2      = (const float*)d_in[10];
    const float* be2     = (const float*)d_in[11];
    float* out = (float*)d_out;

    dim3 tb(32, 8);
    conv_w_kernel<<<(C1 * KIN + 255) / 256, 256>>>(w1, w2);
    transpose_p2_kernel<<<dim3(Sq / 32, D2q / 32, Bq), tb>>>(points2);
    transpose_p1_kernel<<<dim3(Nq / 32, D1q / 32, Bq), tb>>>(points1);
    knn_kernel<<<dim3(Nq / 128, Bq), 128>>>(xyz1, xyz2);
    interp_kernel<<<dim3(Nq / 4, Bq), 256>>>();
    gemm_hmma<1><<<dim3(C1 / 128, MROWS / 128), 256>>>();
    stats_stage1_kernel<<<128, C1>>>(0);
    stats_stage2_kernel<<<1, C1>>>(0, g1, be1);
    bnrelu_split_kernel<<<(MROWS * C1 / 4) / 256, 256>>>();
    gemm_hmma<2><<<dim3(C2 / 128, MROWS / 128), 256>>>();
    stats_stage1_kernel<<<128, C2>>>(1);
    stats_stage2_kernel<<<1, C2>>>(1, g2, be2);
    epilogue_kernel<<<dim3(Nq / 32, C2 / 32, Bq), tb>>>(out);
}

// round 9
// speedup vs baseline: 1.6277x; 1.0482x over previous
#include <cuda_runtime.h>
#include <cuda_bf16.h>
#include <cstdint>

// Problem dims
#define Bq   8
#define Nq   8192
#define Sq   2048
#define D1q  128
#define D2q  256
#define KIN  384          // D1 + D2
#define C1   256          // layer-1 out channels
#define C2   128          // layer-2 out channels
#define MROWS (Bq * Nq)   // 65536

// ---------------------------------------------------------------------------
// Scratch (device globals — no allocation allowed)
// ---------------------------------------------------------------------------
__device__ __align__(16) __nv_bfloat16 g_xh[(size_t)MROWS * KIN];  // bf16 hi (reused [M][256] for GEMM2 A)
__device__ __align__(16) __nv_bfloat16 g_xl[(size_t)MROWS * KIN];  // bf16 lo
__device__ __align__(16) float g_y1 [(size_t)MROWS * C1];          // linear1 out fp32
__device__ __align__(16) float g_y2 [(size_t)MROWS * C2];          // linear2 out fp32
__device__ __align__(16) float g_f2t[(size_t)Bq * Sq * D2q];       // points2 transposed
__device__ int   g_idx[(size_t)Bq * Nq * 3];
__device__ float g_wts[(size_t)Bq * Nq * 3];
__device__ float g_part[128 * 2 * C1];
__device__ float g_scale1[C1], g_shift1[C1];
__device__ float g_scale2[C2], g_shift2[C2];
__device__ __align__(16) __nv_bfloat16 g_w1h[C1 * KIN], g_w1l[C1 * KIN];
__device__ __align__(16) __nv_bfloat16 g_w2h[C2 * C1],  g_w2l[C2 * C1];

// ---------------------------------------------------------------------------
// PTX helpers — ONLY family-portable instructions (sm_80+): cp.async,
// ldmatrix, mma.sync. No tcgen05 anywhere (ptxas here targets plain sm_103).
// ---------------------------------------------------------------------------
__device__ __forceinline__ uint32_t smem_u32(const void* p) {
    uint32_t a;
    asm("{ .reg .u64 t; cvta.to.shared.u64 t, %1; cvt.u32.u64 %0, t; }"
        : "=r"(a) : "l"(p));
    return a;
}
__device__ __forceinline__ void cp16(uint32_t s, const void* g) {
    asm volatile("cp.async.cg.shared.global [%0], [%1], 16;" :: "r"(s), "l"(g) : "memory");
}
__device__ __forceinline__ void cp_commit() {
    asm volatile("cp.async.commit_group;" ::: "memory");
}
template <int N> __device__ __forceinline__ void cp_wait() {
    asm volatile("cp.async.wait_group %0;" :: "n"(N) : "memory");
}
#define LDMX4(r, addr) \
    asm volatile("ldmatrix.sync.aligned.m8n8.x4.shared.b16 {%0,%1,%2,%3}, [%4];" \
        : "=r"((r)[0]), "=r"((r)[1]), "=r"((r)[2]), "=r"((r)[3]) : "r"(addr))

__device__ __forceinline__ void mma16816(float* d, const uint32_t* a,
                                         uint32_t b0, uint32_t b1) {
    asm volatile(
        "mma.sync.aligned.m16n8k16.row.col.f32.bf16.bf16.f32 "
        "{%0,%1,%2,%3}, {%4,%5,%6,%7}, {%8,%9}, {%0,%1,%2,%3};"
        : "+f"(d[0]), "+f"(d[1]), "+f"(d[2]), "+f"(d[3])
        : "r"(a[0]), "r"(a[1]), "r"(a[2]), "r"(a[3]), "r"(b0), "r"(b1));
}

__device__ __forceinline__ void bf16_split(float v, __nv_bfloat16& h, __nv_bfloat16& l) {
    h = __float2bfloat16(v);
    l = __float2bfloat16(v - __bfloat162float(h));
}

// ---------------------------------------------------------------------------
// Weight pre-split: fp32 -> bf16 hi/lo
// ---------------------------------------------------------------------------
__global__ void conv_w_kernel(const float* __restrict__ w1, const float* __restrict__ w2) {
    int i = blockIdx.x * 256 + threadIdx.x;
    if (i < C1 * KIN) {
        __nv_bfloat16 h, l; bf16_split(w1[i], h, l);
        g_w1h[i] = h; g_w1l[i] = l;
    }
    if (i < C2 * C1) {
        __nv_bfloat16 h, l; bf16_split(w2[i], h, l);
        g_w2h[i] = h; g_w2l[i] = l;
    }
}

// ---------------------------------------------------------------------------
// Transpose points2 [B, D2, S] -> g_f2t [B, S, D2]
// ---------------------------------------------------------------------------
__global__ void transpose_p2_kernel(const float* __restrict__ p2) {
    __shared__ float tile[32][33];
    int b  = blockIdx.z;
    int s0 = blockIdx.x * 32, d0 = blockIdx.y * 32;
    int tx = threadIdx.x, ty = threadIdx.y;
    const float* src = p2 + (size_t)b * D2q * Sq;
    #pragma unroll
    for (int i = ty; i < 32; i += 8)
        tile[i][tx] = src[(size_t)(d0 + i) * Sq + s0 + tx];
    __syncthreads();
    float* dst = g_f2t + (size_t)b * Sq * D2q;
    #pragma unroll
    for (int i = ty; i < 32; i += 8)
        dst[(size_t)(s0 + i) * D2q + d0 + tx] = tile[tx][i];
}

// ---------------------------------------------------------------------------
// Transpose points1 [B, D1, N] -> g_xh/g_xl columns [0, 128)
// ---------------------------------------------------------------------------
__global__ void transpose_p1_kernel(const float* __restrict__ p1) {
    __shared__ float tile[32][33];
    int b  = blockIdx.z;
    int n0 = blockIdx.x * 32, d0 = blockIdx.y * 32;
    int tx = threadIdx.x, ty = threadIdx.y;
    const float* src = p1 + (size_t)b * D1q * Nq;
    #pragma unroll
    for (int i = ty; i < 32; i += 8)
        tile[i][tx] = src[(size_t)(d0 + i) * Nq + n0 + tx];
    __syncthreads();
    #pragma unroll
    for (int i = ty; i < 32; i += 8) {
        float v = tile[tx][i];
        __nv_bfloat16 h, l; bf16_split(v, h, l);
        size_t o = ((size_t)b * Nq + n0 + i) * KIN + d0 + tx;
        g_xh[o] = h; g_xl[o] = l;
    }
}

// ---------------------------------------------------------------------------
// 3-NN + weights. 256 threads = 128 points x 2 half-scans of S.
// Candidates packed (x,y,z,|p|^2) in one float4 -> single LDS.128 per iter.
// Query norm n1 deferred out of the loop (constant shift preserves order).
// Halves merged with the same strict-< insertion (tie semantics preserved:
// half-1 indices are always larger; strict < keeps the earlier index).
// ---------------------------------------------------------------------------
__global__ __launch_bounds__(256) void knn_kernel(const float* __restrict__ xyz1,
                                                  const float* __restrict__ xyz2) {
    __shared__ float4 sp[Sq];          // 32 KB
    __shared__ float  sd[3 * 128];
    __shared__ int    si[3 * 128];
    int b = blockIdx.y;
    const float* x2 = xyz2 + (size_t)b * 3 * Sq;
    for (int s = threadIdx.x; s < Sq; s += 256) {
        float xx = x2[s], yy = x2[Sq + s], zz = x2[2 * Sq + s];
        float4 c = { xx, yy, zz, fmaf(xx, xx, fmaf(yy, yy, zz * zz)) };
        sp[s] = c;
    }
    __syncthreads();

    const int half = threadIdx.x >> 7;       // 0 or 1
    const int pt   = threadIdx.x & 127;
    const int n    = blockIdx.x * 128 + pt;
    const float* x1 = xyz1 + (size_t)b * 3 * Nq;
    const float px = x1[n], py = x1[Nq + n], pz = x1[2 * Nq + n];

    float d0 = 3.4e38f, d1 = 3.4e38f, d2 = 3.4e38f;
    int   i0 = 0, i1 = 0, i2 = 0;
    const int s0 = half * (Sq / 2);
    #pragma unroll 4
    for (int s = s0; s < s0 + Sq / 2; s++) {
        float4 c = sp[s];
        float dot = fmaf(px, c.x, fmaf(py, c.y, pz * c.z));
        float d   = fmaf(-2.0f, dot, c.w);            // d_true - n1 (order-equal)
        if (d < d2) {
            if (d < d1) {
                d2 = d1; i2 = i1;
                if (d < d0) { d1 = d0; i1 = i0; d0 = d; i0 = s; }
                else        { d1 = d;  i1 = s; }
            } else { d2 = d; i2 = s; }
        }
    }

    if (half == 1) {
        sd[pt] = d0; sd[128 + pt] = d1; sd[256 + pt] = d2;
        si[pt] = i0; si[128 + pt] = i1; si[256 + pt] = i2;
    }
    __syncthreads();
    if (half == 0) {
        #pragma unroll
        for (int j = 0; j < 3; j++) {
            float d = sd[j * 128 + pt];
            int   ix = si[j * 128 + pt];
            if (d < d2) {
                if (d < d1) {
                    d2 = d1; i2 = i1;
                    if (d < d0) { d1 = d0; i1 = i0; d0 = d; i0 = ix; }
                    else        { d1 = d;  i1 = ix; }
                } else { d2 = d; i2 = ix; }
            }
        }
        float n1 = fmaf(px, px, fmaf(py, py, pz * pz));
        d0 = fmaxf(d0 + n1, 1e-10f);
        d1 = fmaxf(d1 + n1, 1e-10f);
        d2 = fmaxf(d2 + n1, 1e-10f);
        float w0 = 1.0f / d0, w1 = 1.0f / d1, w2 = 1.0f / d2;
        float inv = 1.0f / (w0 + w1 + w2);
        size_t base = ((size_t)b * Nq + n) * 3;
        g_idx[base] = i0; g_idx[base + 1] = i1; g_idx[base + 2] = i2;
        g_wts[base] = w0 * inv; g_wts[base + 1] = w1 * inv; g_wts[base + 2] = w2 * inv;
    }
}

// ---------------------------------------------------------------------------
// Interpolate -> g_xh/g_xl columns [128, 384). 64 threads per point, float4.
// ---------------------------------------------------------------------------
__global__ void interp_kernel() {
    int b  = blockIdx.y;
    int pt = blockIdx.x * 4 + (threadIdx.x >> 6);
    int t  = threadIdx.x & 63;
    size_t qb = (size_t)b * Nq + pt;
    const int*   ip = g_idx + qb * 3;
    const float* wp = g_wts + qb * 3;
    const float* f  = g_f2t + (size_t)b * Sq * D2q;
    int d = t * 4;
    float4 f0 = *(const float4*)(f + (size_t)ip[0] * D2q + d);
    float4 f1 = *(const float4*)(f + (size_t)ip[1] * D2q + d);
    float4 f2 = *(const float4*)(f + (size_t)ip[2] * D2q + d);
    float w0 = wp[0], w1 = wp[1], w2 = wp[2];
    float a0 = fmaf(w2, f2.x, fmaf(w1, f1.x, w0 * f0.x));
    float a1 = fmaf(w2, f2.y, fmaf(w1, f1.y, w0 * f0.y));
    float a2 = fmaf(w2, f2.z, fmaf(w1, f1.z, w0 * f0.z));
    float a3 = fmaf(w2, f2.w, fmaf(w1, f1.w, w0 * f0.w));
    __nv_bfloat16 h0, l0, h1, l1, h2, l2, h3, l3;
    bf16_split(a0, h0, l0); bf16_split(a1, h1, l1);
    bf16_split(a2, h2, l2); bf16_split(a3, h3, l3);
    uint32_t ph0 = ((uint32_t)__bfloat16_as_ushort(h1) << 16) | __bfloat16_as_ushort(h0);
    uint32_t ph1 = ((uint32_t)__bfloat16_as_ushort(h3) << 16) | __bfloat16_as_ushort(h2);
    uint32_t pl0 = ((uint32_t)__bfloat16_as_ushort(l1) << 16) | __bfloat16_as_ushort(l0);
    uint32_t pl1 = ((uint32_t)__bfloat16_as_ushort(l3) << 16) | __bfloat16_as_ushort(l2);
    uint2 vh = {ph0, ph1}, vl = {pl0, pl1};
    size_t o = qb * KIN + D1q + d;
    *(uint2*)(g_xh + o) = vh;
    *(uint2*)(g_xl + o) = vl;
}

// ---------------------------------------------------------------------------
// HMMA GEMM (mma.sync m16n8k16 bf16 -> f32), 3-pass hi/lo split.
// Block 128x128, 8 warps (4 M x 2 N), warp tile 32x64, K-chunk 32,
// cp.async double buffer, 80B-padded SMEM rows (conflict-free ldmatrix).
// WHICH=1: y1[M,256] = x[M,384] @ w1^T     (A=g_xh/g_xl LDA=384)
// WHICH=2: y2[M,128] = a2[M,256] @ w2^T    (A=reused g_xh/g_xl LDA=256)
// ---------------------------------------------------------------------------
template <int WHICH>
__global__ __launch_bounds__(256) void gemm_hmma() {
    constexpr int LDA = (WHICH == 1) ? KIN : C1;
    constexpr int LDB = (WHICH == 1) ? KIN : C1;
    constexpr int KD  = (WHICH == 1) ? KIN : C1;
    constexpr int LDC = (WHICH == 1) ? C1  : C2;
    constexpr int KC  = KD / 32;
    constexpr int NITER = 3 * KC;

    const __nv_bfloat16* Ah = g_xh;
    const __nv_bfloat16* Al = g_xl;
    const __nv_bfloat16* Bh = (WHICH == 1) ? g_w1h : g_w2h;
    const __nv_bfloat16* Bl = (WHICH == 1) ? g_w1l : g_w2l;
    float* Cout = (WHICH == 1) ? g_y1 : g_y2;

    __shared__ __align__(16) char smA[2][128 * 80];
    __shared__ __align__(16) char smB[2][128 * 80];

    const int tid = threadIdx.x, lane = tid & 31, wid = tid >> 5;
    const int warp_m = wid & 3, warp_n = wid >> 2;
    const size_t row0 = (size_t)blockIdx.y * 128;
    const int col0 = blockIdx.x * 128;

    const uint32_t sAu[2] = { smem_u32(smA[0]), smem_u32(smA[1]) };
    const uint32_t sBu[2] = { smem_u32(smB[0]), smem_u32(smB[1]) };

    // ldmatrix per-lane base offsets (bytes)
    const uint32_t a_off = (uint32_t)((warp_m * 32 + ((lane >> 3) & 1) * 8 + (lane & 7)) * 80
                                      + (lane >> 4) * 16);
    const uint32_t b_off = (uint32_t)((warp_n * 64 + (lane >> 4) * 8 + (lane & 7)) * 80
                                      + ((lane >> 3) & 1) * 16);

    float acc[2][8][4] = {};

    auto issue = [&](int it, int buf) {
        const int p  = it / KC;
        const int k0 = (it - p * KC) * 32;
        const char* As = (const char*)((p == 1) ? Al : Ah);
        const char* Bs = (const char*)((p == 2) ? Bl : Bh);
        #pragma unroll
        for (int i = 0; i < 2; i++) {
            int c = tid + i * 256;
            int r = c >> 2, cc = c & 3;
            cp16(sAu[buf] + r * 80 + cc * 16,
                 As + ((row0 + r) * LDA + k0) * 2 + cc * 16);
            cp16(sBu[buf] + r * 80 + cc * 16,
                 Bs + ((size_t)(col0 + r) * LDB + k0) * 2 + cc * 16);
        }
        cp_commit();
    };

    issue(0, 0);
    for (int it = 0; it < NITER; it++) {
        const int buf = it & 1;
        if (it + 1 < NITER) { issue(it + 1, buf ^ 1); cp_wait<1>(); }
        else                { cp_wait<0>(); }
        __syncthreads();

        #pragma unroll
        for (int ks = 0; ks < 2; ks++) {
            uint32_t af[2][4];
            LDMX4(af[0], sAu[buf] + a_off + ks * 32);
            LDMX4(af[1], sAu[buf] + a_off + 16 * 80 + ks * 32);
            uint32_t bfr[4][4];
            #pragma unroll
            for (int jp = 0; jp < 4; jp++)
                LDMX4(bfr[jp], sBu[buf] + b_off + jp * 16 * 80 + ks * 32);
            #pragma unroll
            for (int mt = 0; mt < 2; mt++)
                #pragma unroll
                for (int j = 0; j < 8; j++)
                    mma16816(acc[mt][j], af[mt],
                             bfr[j >> 1][(j & 1) * 2], bfr[j >> 1][(j & 1) * 2 + 1]);
        }
        __syncthreads();
    }

    // Store: c0,c1 -> (row, col..col+1); c2,c3 -> (row+8, ...)
    #pragma unroll
    for (int mt = 0; mt < 2; mt++) {
        #pragma unroll
        for (int j = 0; j < 8; j++) {
            size_t row = row0 + warp_m * 32 + mt * 16 + (lane >> 2);
            int    col = col0 + warp_n * 64 + j * 8 + 2 * (lane & 3);
            float* p0 = Cout + row * LDC + col;
            float2 v0 = { acc[mt][j][0], acc[mt][j][1] };
            float2 v1 = { acc[mt][j][2], acc[mt][j][3] };
            *(float2*)p0 = v0;
            *(float2*)(p0 + 8 * LDC) = v1;
        }
    }
}

// ---------------------------------------------------------------------------
// BN stats (two deterministic stages)
// ---------------------------------------------------------------------------
__global__ void stats_stage1_kernel(int layer) {
    int C = layer ? C2 : C1;
    const float* Y = layer ? g_y2 : g_y1;
    int ch = threadIdx.x;
    size_t r0 = (size_t)blockIdx.x * 512;
    float s = 0.0f, sq = 0.0f;
    for (int r = 0; r < 512; r++) {
        float v = Y[(r0 + r) * C + ch];
        s += v;
        sq = fmaf(v, v, sq);
    }
    g_part[blockIdx.x * 2 * C + ch]     = s;
    g_part[blockIdx.x * 2 * C + C + ch] = sq;
}

__global__ void stats_stage2_kernel(int layer, const float* __restrict__ g,
                                    const float* __restrict__ be) {
    int C  = layer ? C2 : C1;
    int ch = threadIdx.x;
    float s = 0.0f, sq = 0.0f;
    for (int bk = 0; bk < 128; bk++) {
        s  += g_part[bk * 2 * C + ch];
        sq += g_part[bk * 2 * C + C + ch];
    }
    const float invM = 1.0f / (float)MROWS;
    float mean = s * invM;
    float var  = fmaf(sq, invM, -mean * mean);
    float scv  = g[ch] * rsqrtf(var + 1e-5f);
    float shv  = fmaf(-mean, scv, be[ch]);
    if (layer) { g_scale2[ch] = scv; g_shift2[ch] = shv; }
    else       { g_scale1[ch] = scv; g_shift1[ch] = shv; }
}

// ---------------------------------------------------------------------------
// BN+ReLU+bf16-split of y1 -> g_xh/g_xl reused as [M][256] (GEMM2 A operand)
// ---------------------------------------------------------------------------
__global__ void bnrelu_split_kernel() {
    size_t i = ((size_t)blockIdx.x * 256 + threadIdx.x) * 4;  // over MROWS*C1
    float4 v = *(const float4*)(g_y1 + i);
    int ch = (int)(i & (C1 - 1));
    float a0 = fmaxf(fmaf(v.x, g_scale1[ch],     g_shift1[ch]),     0.0f);
    float a1 = fmaxf(fmaf(v.y, g_scale1[ch + 1], g_shift1[ch + 1]), 0.0f);
    float a2 = fmaxf(fmaf(v.z, g_scale1[ch + 2], g_shift1[ch + 2]), 0.0f);
    float a3 = fmaxf(fmaf(v.w, g_scale1[ch + 3], g_shift1[ch + 3]), 0.0f);
    __nv_bfloat16 h0, l0, h1, l1, h2, l2, h3, l3;
    bf16_split(a0, h0, l0); bf16_split(a1, h1, l1);
    bf16_split(a2, h2, l2); bf16_split(a3, h3, l3);
    uint32_t ph0 = ((uint32_t)__bfloat16_as_ushort(h1) << 16) | __bfloat16_as_ushort(h0);
    uint32_t ph1 = ((uint32_t)__bfloat16_as_ushort(h3) << 16) | __bfloat16_as_ushort(h2);
    uint32_t pl0 = ((uint32_t)__bfloat16_as_ushort(l1) << 16) | __bfloat16_as_ushort(l0);
    uint32_t pl1 = ((uint32_t)__bfloat16_as_ushort(l3) << 16) | __bfloat16_as_ushort(l2);
    uint2 vh = {ph0, ph1}, vl = {pl0, pl1};
    *(uint2*)(g_xh + i) = vh;
    *(uint2*)(g_xl + i) = vl;
}

// ---------------------------------------------------------------------------
// Final epilogue: out[b, c, n] = relu(bn2(y2)), transposed write
// ---------------------------------------------------------------------------
__global__ void epilogue_kernel(float* __restrict__ out) {
    __shared__ float tile[32][33];
    int b  = blockIdx.z;
    int n0 = blockIdx.x * 32, c0 = blockIdx.y * 32;
    int tx = threadIdx.x, ty = threadIdx.y;
    #pragma unroll
    for (int i = ty; i < 32; i += 8) {
        float v = g_y2[((size_t)b * Nq + n0 + i) * C2 + c0 + tx];
        tile[i][tx] = fmaxf(fmaf(v, g_scale2[c0 + tx], g_shift2[c0 + tx]), 0.0f);
    }
    __syncthreads();
    #pragma unroll
    for (int i = ty; i < 32; i += 8)
        out[(size_t)b * C2 * Nq + (size_t)(c0 + i) * Nq + n0 + tx] = tile[tx][i];
}

// ---------------------------------------------------------------------------
// Launch
// ---------------------------------------------------------------------------
extern "C" void kernel_launch(void* const* d_in, const int* in_sizes, int n_in,
                              void* d_out, int out_size) {
    const float* xyz1    = (const float*)d_in[0];
    const float* xyz2    = (const float*)d_in[1];
    const float* points1 = (const float*)d_in[2];
    const float* points2 = (const float*)d_in[3];
    const float* w1      = (const float*)d_in[4];
    const float* g1      = (const float*)d_in[6];
    const float* be1     = (const float*)d_in[7];
    const float* w2      = (const float*)d_in[8];
    const float* g2      = (const float*)d_in[10];
    const float* be2     = (const float*)d_in[11];
    float* out = (float*)d_out;

    dim3 tb(32, 8);
    conv_w_kernel<<<(C1 * KIN + 255) / 256, 256>>>(w1, w2);
    transpose_p2_kernel<<<dim3(Sq / 32, D2q / 32, Bq), tb>>>(points2);
    transpose_p1_kernel<<<dim3(Nq / 32, D1q / 32, Bq), tb>>>(points1);
    knn_kernel<<<dim3(Nq / 128, Bq), 256>>>(xyz1, xyz2);
    interp_kernel<<<dim3(Nq / 4, Bq), 256>>>();
    gemm_hmma<1><<<dim3(C1 / 128, MROWS / 128), 256>>>();
    stats_stage1_kernel<<<128, C1>>>(0);
    stats_stage2_kernel<<<1, C1>>>(0, g1, be1);
    bnrelu_split_kernel<<<(MROWS * C1 / 4) / 256, 256>>>();
    gemm_hmma<2><<<dim3(C2 / 128, MROWS / 128), 256>>>();
    stats_stage1_kernel<<<128, C2>>>(1);
    stats_stage2_kernel<<<1, C2>>>(1, g2, be2);
    epilogue_kernel<<<dim3(Nq / 32, C2 / 32, Bq), tb>>>(out);
}